// round 5
// baseline (speedup 1.0000x reference)
#include <cuda_runtime.h>

// NeuS volume-rendering composite.
// Key identity: alpha_i = (sig_i - sig_{i+1})/sig_i  =>  1-alpha_i = sig_{i+1}/sig_i
//   trans_i = cumprod_{j<i}(1-alpha_j) = sig_i / sig_0            (telescopes)
//   weight_i = trans_i * clip(alpha_i,0,1) = max(sig_i - sig_{i+1}, 0) / sig_0
// with weight_0 = 0 (prepended zero transmittance) and weight_{S-1} = 0 (appended zero alpha).
// So the whole per-ray scan collapses to local arithmetic + one broadcast of sig_0.

constexpr int N_RAYS    = 65536;
constexpr int N_SAMPLES = 128;

__device__ __forceinline__ float sigmoidf(float x) {
    // x*s bounded ~ +-20 for these inputs; __expf is safe and ~2 ulp.
    return 1.0f / (1.0f + __expf(-x));
}

__global__ __launch_bounds__(256)
void neus_render_kernel(const float* __restrict__ sdf,
                        const float* __restrict__ color,
                        const float* __restrict__ z_vals,
                        const float* __restrict__ s_ptr,
                        const float* __restrict__ bg,
                        float* __restrict__ out)
{
    const int gtid = blockIdx.x * blockDim.x + threadIdx.x;
    const int ray  = gtid >> 5;          // one warp per ray
    const int lane = gtid & 31;
    if (ray >= N_RAYS) return;

    const float s = __ldg(s_ptr);

    // ---- load 4 contiguous sdf samples (fully coalesced float4) ----
    const float4 sd = __ldg(reinterpret_cast<const float4*>(sdf) + ray * 32 + lane);

    float sig0 = sigmoidf(sd.x * s);
    float sig1 = sigmoidf(sd.y * s);
    float sig2 = sigmoidf(sd.z * s);
    float sig3 = sigmoidf(sd.w * s);

    // neighbor lane's first sigmoid = sample 4*lane+4 (lane 31's value unused)
    const float sig_next = __shfl_down_sync(0xffffffffu, sig0, 1);
    // ray's first sigmoid -> broadcast, one reciprocal per ray
    const float sig_ray0 = __shfl_sync(0xffffffffu, sig0, 0);
    const float inv_s0   = 1.0f / sig_ray0;

    // ---- weights (weight_0 = 0, weight_127 = 0) ----
    float w0 = (lane == 0)  ? 0.0f : fmaxf(sig0 - sig1, 0.0f) * inv_s0;
    float w1 =                       fmaxf(sig1 - sig2, 0.0f) * inv_s0;
    float w2 =                       fmaxf(sig2 - sig3, 0.0f) * inv_s0;
    float w3 = (lane == 31) ? 0.0f : fmaxf(sig3 - sig_next, 0.0f) * inv_s0;

    // ---- store weight tile (aligned float4) ----
    float* w_out = out + N_RAYS * 4;                    // after pixel[R,3] + invdepth[R]
    reinterpret_cast<float4*>(w_out)[ray * 32 + lane] = make_float4(w0, w1, w2, w3);

    // ---- inverse depth ----
    const float4 z4 = __ldg(reinterpret_cast<const float4*>(z_vals) + ray * 32 + lane);
    float invd = w0 / z4.x + w1 / z4.y + w2 / z4.z + w3 / z4.w;

    // ---- color accumulation: 12 contiguous floats per lane = 3 aligned float4 ----
    const float4* cp = reinterpret_cast<const float4*>(color) + ray * 96 + lane * 3;
    const float4 c0 = __ldg(cp + 0);   // r0 g0 b0 r1
    const float4 c1 = __ldg(cp + 1);   // g1 b1 r2 g2
    const float4 c2 = __ldg(cp + 2);   // b2 r3 g3 b3

    float pr = w0 * c0.x + w1 * c0.w + w2 * c1.z + w3 * c2.y;
    float pg = w0 * c0.y + w1 * c1.x + w2 * c1.w + w3 * c2.z;
    float pb = w0 * c0.z + w1 * c1.y + w2 * c2.x + w3 * c2.w;
    float ws = w0 + w1 + w2 + w3;

    // ---- warp butterfly reduction over 5 scalars ----
    #pragma unroll
    for (int off = 16; off > 0; off >>= 1) {
        pr   += __shfl_xor_sync(0xffffffffu, pr,   off);
        pg   += __shfl_xor_sync(0xffffffffu, pg,   off);
        pb   += __shfl_xor_sync(0xffffffffu, pb,   off);
        invd += __shfl_xor_sync(0xffffffffu, invd, off);
        ws   += __shfl_xor_sync(0xffffffffu, ws,   off);
    }

    if (lane == 0) {
        const float resid = 1.0f - ws;
        const float bg0 = __ldg(bg + 0);
        const float bg1 = __ldg(bg + 1);
        const float bg2 = __ldg(bg + 2);
        out[ray * 3 + 0]      = pr + resid * bg0;   // pixel
        out[ray * 3 + 1]      = pg + resid * bg1;
        out[ray * 3 + 2]      = pb + resid * bg2;
        out[N_RAYS * 3 + ray] = invd;               // invdepth
    }
}

extern "C" void kernel_launch(void* const* d_in, const int* in_sizes, int n_in,
                              void* d_out, int out_size)
{
    const float* sdf   = (const float*)d_in[0];
    const float* color = (const float*)d_in[1];
    const float* z     = (const float*)d_in[2];
    const float* s     = (const float*)d_in[3];
    const float* bg    = (const float*)d_in[4];
    float* out = (float*)d_out;

    // 1 warp per ray, 8 warps per block
    const int threads = 256;
    const int blocks  = (N_RAYS * 32) / threads;   // 8192
    neus_render_kernel<<<blocks, threads>>>(sdf, color, z, s, bg, out);
}

// round 6
// speedup vs baseline: 1.0969x; 1.0969x over previous
#include <cuda_runtime.h>

// NeuS volume-rendering composite, telescoped:
//   1 - alpha_i = sig_{i+1}/sig_i  =>  trans_i = sig_i / sig_0
//   weight_i = max(sig_i - sig_{i+1}, 0) / sig_0,  weight_0 = weight_{S-1} = 0.
//
// Layout: 2 rays per warp (16-lane segments). Sub-lane sl owns samples
// [4sl..4sl+3] (group A) and [64+4sl..64+4sl+3] (group B) -> all loads are
// aligned float4, reductions are width-16 butterflies (4 levels x 4 scalars).
// Background folded into the color sum: pixel = bg + sum w*(c - bg), which
// removes the weight-sum reduction entirely.

constexpr int N_RAYS    = 65536;
constexpr int N_SAMPLES = 128;

__device__ __forceinline__ float sigmoidf(float x) {
    return 1.0f / (1.0f + __expf(-x));
}

__global__ __launch_bounds__(256)
void neus_render_kernel(const float* __restrict__ sdf,
                        const float* __restrict__ color,
                        const float* __restrict__ z_vals,
                        const float* __restrict__ s_ptr,
                        const float* __restrict__ bg,
                        float* __restrict__ out)
{
    const int gtid = blockIdx.x * blockDim.x + threadIdx.x;
    const int lane = gtid & 31;
    const int sl   = lane & 15;                 // sub-lane within 16-lane segment
    const int ray  = (gtid >> 5) * 2 + (lane >> 4);   // 2 rays per warp

    const float s   = __ldg(s_ptr);
    const float bg0 = __ldg(bg + 0);
    const float bg1 = __ldg(bg + 1);
    const float bg2 = __ldg(bg + 2);

    // ---- front-batched loads: 10 aligned LDG.128 per thread ----
    const int r32 = ray * 32;                   // float4 index base for sdf/z/weight
    const float4* sp = reinterpret_cast<const float4*>(sdf);
    const float4* zp = reinterpret_cast<const float4*>(z_vals);
    const float4* cp = reinterpret_cast<const float4*>(color) + ray * 96;

    const float4 sdA = __ldg(sp + r32 + sl);         // samples 4sl..4sl+3
    const float4 sdB = __ldg(sp + r32 + 16 + sl);    // samples 64+4sl..64+4sl+3
    const float4 zA  = __ldg(zp + r32 + sl);
    const float4 zB  = __ldg(zp + r32 + 16 + sl);
    const float4 cA0 = __ldg(cp + sl * 3 + 0);       // r0 g0 b0 r1
    const float4 cA1 = __ldg(cp + sl * 3 + 1);       // g1 b1 r2 g2
    const float4 cA2 = __ldg(cp + sl * 3 + 2);       // b2 r3 g3 b3
    const float4 cB0 = __ldg(cp + 48 + sl * 3 + 0);
    const float4 cB1 = __ldg(cp + 48 + sl * 3 + 1);
    const float4 cB2 = __ldg(cp + 48 + sl * 3 + 2);

    // ---- sigmoids ----
    const float a0 = sigmoidf(sdA.x * s), a1 = sigmoidf(sdA.y * s);
    const float a2 = sigmoidf(sdA.z * s), a3 = sigmoidf(sdA.w * s);
    const float b0 = sigmoidf(sdB.x * s), b1 = sigmoidf(sdB.y * s);
    const float b2 = sigmoidf(sdB.z * s), b3 = sigmoidf(sdB.w * s);

    // ---- segment shuffles (width=16) ----
    const unsigned FULL = 0xffffffffu;
    const float a0_next  = __shfl_down_sync(FULL, a0, 1, 16);  // sig(4sl+4), valid sl<15
    const float b0_next  = __shfl_down_sync(FULL, b0, 1, 16);  // sig(64+4sl+4), valid sl<15
    const float b0_first = __shfl_sync(FULL, b0, 0, 16);       // sig(sample 64)
    const float sig0     = __shfl_sync(FULL, a0, 0, 16);       // sig(sample 0)
    const float inv_s0   = 1.0f / sig0;

    const float nextA = (sl == 15) ? b0_first : a0_next;       // sample after 4sl+3

    // ---- weights ----
    const float wa0 = (sl == 0) ? 0.0f : fmaxf(a0 - a1, 0.0f) * inv_s0;
    const float wa1 = fmaxf(a1 - a2,    0.0f) * inv_s0;
    const float wa2 = fmaxf(a2 - a3,    0.0f) * inv_s0;
    const float wa3 = fmaxf(a3 - nextA, 0.0f) * inv_s0;
    const float wb0 = fmaxf(b0 - b1,    0.0f) * inv_s0;
    const float wb1 = fmaxf(b1 - b2,    0.0f) * inv_s0;
    const float wb2 = fmaxf(b2 - b3,    0.0f) * inv_s0;
    const float wb3 = (sl == 15) ? 0.0f : fmaxf(b3 - b0_next, 0.0f) * inv_s0;

    // ---- store weight tiles (aligned STG.128) ----
    float4* w_out = reinterpret_cast<float4*>(out + N_RAYS * 4);
    w_out[r32 + sl]      = make_float4(wa0, wa1, wa2, wa3);
    w_out[r32 + 16 + sl] = make_float4(wb0, wb1, wb2, wb3);

    // ---- inverse depth partial ----
    float invd = wa0 / zA.x + wa1 / zA.y + wa2 / zA.z + wa3 / zA.w
               + wb0 / zB.x + wb1 / zB.y + wb2 / zB.z + wb3 / zB.w;

    // ---- pixel partials with background folded in ----
    float pr = wa0 * (cA0.x - bg0) + wa1 * (cA0.w - bg0)
             + wa2 * (cA1.z - bg0) + wa3 * (cA2.y - bg0)
             + wb0 * (cB0.x - bg0) + wb1 * (cB0.w - bg0)
             + wb2 * (cB1.z - bg0) + wb3 * (cB2.y - bg0);
    float pg = wa0 * (cA0.y - bg1) + wa1 * (cA1.x - bg1)
             + wa2 * (cA1.w - bg1) + wa3 * (cA2.z - bg1)
             + wb0 * (cB0.y - bg1) + wb1 * (cB1.x - bg1)
             + wb2 * (cB1.w - bg1) + wb3 * (cB2.z - bg1);
    float pb = wa0 * (cA0.z - bg2) + wa1 * (cA1.y - bg2)
             + wa2 * (cA2.x - bg2) + wa3 * (cA2.w - bg2)
             + wb0 * (cB0.z - bg2) + wb1 * (cB1.y - bg2)
             + wb2 * (cB2.x - bg2) + wb3 * (cB2.w - bg2);

    // ---- width-16 butterfly over 4 scalars (16 SHFL per warp / 2 rays) ----
    #pragma unroll
    for (int off = 8; off > 0; off >>= 1) {
        pr   += __shfl_xor_sync(FULL, pr,   off, 16);
        pg   += __shfl_xor_sync(FULL, pg,   off, 16);
        pb   += __shfl_xor_sync(FULL, pb,   off, 16);
        invd += __shfl_xor_sync(FULL, invd, off, 16);
    }

    if (sl == 0) {
        out[ray * 3 + 0]      = bg0 + pr;
        out[ray * 3 + 1]      = bg1 + pg;
        out[ray * 3 + 2]      = bg2 + pb;
        out[N_RAYS * 3 + ray] = invd;
    }
}

extern "C" void kernel_launch(void* const* d_in, const int* in_sizes, int n_in,
                              void* d_out, int out_size)
{
    const float* sdf   = (const float*)d_in[0];
    const float* color = (const float*)d_in[1];
    const float* z     = (const float*)d_in[2];
    const float* s     = (const float*)d_in[3];
    const float* bg    = (const float*)d_in[4];
    float* out = (float*)d_out;

    // 2 rays per warp, 8 warps per block -> 16 rays per block
    const int threads = 256;
    const int blocks  = N_RAYS / 16;   // 4096
    neus_render_kernel<<<blocks, threads>>>(sdf, color, z, s, bg, out);
}

// round 10
// speedup vs baseline: 1.1151x; 1.0166x over previous
#include <cuda_runtime.h>

// NeuS volume-rendering composite, telescoped:
//   1 - alpha_i = sig_{i+1}/sig_i  =>  trans_i = sig_i / sig_0
//   weight_i = max(sig_i - sig_{i+1}, 0) / sig_0,  weight_0 = weight_{S-1} = 0.
//
// 2 rays per warp (16-lane segments); sub-lane sl owns samples [4sl..4sl+3]
// and [64+4sl..64+4sl+3]. All global accesses are aligned float4.
// Background folded into the color sum: pixel = bg + sum w*(c - bg).
// All divisions via __fdividef (MUFU.RCP fast path) — kills the IEEE-divide
// Newton fixup FFMAs + temp registers; __launch_bounds__(256,5) caps regs at
// 51 so 5 blocks/SM (40 warps) fit instead of 4 (32).

constexpr int N_RAYS    = 65536;
constexpr int N_SAMPLES = 128;

__device__ __forceinline__ float fsigmoid(float x) {
    return __fdividef(1.0f, 1.0f + __expf(-x));
}

__global__ __launch_bounds__(256, 5)
void neus_render_kernel(const float* __restrict__ sdf,
                        const float* __restrict__ color,
                        const float* __restrict__ z_vals,
                        const float* __restrict__ s_ptr,
                        const float* __restrict__ bg,
                        float* __restrict__ out)
{
    const int gtid = blockIdx.x * blockDim.x + threadIdx.x;
    const int lane = gtid & 31;
    const int sl   = lane & 15;                       // sub-lane in 16-lane segment
    const int ray  = (gtid >> 5) * 2 + (lane >> 4);   // 2 rays per warp

    const float s   = __ldg(s_ptr);
    const float bg0 = __ldg(bg + 0);
    const float bg1 = __ldg(bg + 1);
    const float bg2 = __ldg(bg + 2);

    // ---- front-batched loads: 10 aligned LDG.128 per thread ----
    const int r32 = ray * 32;
    const float4* sp = reinterpret_cast<const float4*>(sdf);
    const float4* zp = reinterpret_cast<const float4*>(z_vals);
    const float4* cp = reinterpret_cast<const float4*>(color) + ray * 96;

    const float4 sdA = __ldg(sp + r32 + sl);
    const float4 sdB = __ldg(sp + r32 + 16 + sl);
    const float4 zA  = __ldg(zp + r32 + sl);
    const float4 zB  = __ldg(zp + r32 + 16 + sl);
    const float4 cA0 = __ldg(cp + sl * 3 + 0);        // r0 g0 b0 r1
    const float4 cA1 = __ldg(cp + sl * 3 + 1);        // g1 b1 r2 g2
    const float4 cA2 = __ldg(cp + sl * 3 + 2);        // b2 r3 g3 b3
    const float4 cB0 = __ldg(cp + 48 + sl * 3 + 0);
    const float4 cB1 = __ldg(cp + 48 + sl * 3 + 1);
    const float4 cB2 = __ldg(cp + 48 + sl * 3 + 2);

    // ---- sigmoids ----
    const float a0 = fsigmoid(sdA.x * s), a1 = fsigmoid(sdA.y * s);
    const float a2 = fsigmoid(sdA.z * s), a3 = fsigmoid(sdA.w * s);
    const float b0 = fsigmoid(sdB.x * s), b1 = fsigmoid(sdB.y * s);
    const float b2 = fsigmoid(sdB.z * s), b3 = fsigmoid(sdB.w * s);

    // ---- segment shuffles (width=16) ----
    const unsigned FULL = 0xffffffffu;
    const float a0_next  = __shfl_down_sync(FULL, a0, 1, 16);  // sig(4sl+4)
    const float b0_next  = __shfl_down_sync(FULL, b0, 1, 16);  // sig(64+4sl+4)
    const float b0_first = __shfl_sync(FULL, b0, 0, 16);       // sig(sample 64)
    const float sig0     = __shfl_sync(FULL, a0, 0, 16);       // sig(sample 0)
    const float inv_s0   = __fdividef(1.0f, sig0);

    const float nextA = (sl == 15) ? b0_first : a0_next;

    // ---- weights (weight_0 = 0, weight_127 = 0) ----
    const float wa0 = (sl == 0) ? 0.0f : fmaxf(a0 - a1, 0.0f) * inv_s0;
    const float wa1 = fmaxf(a1 - a2,    0.0f) * inv_s0;
    const float wa2 = fmaxf(a2 - a3,    0.0f) * inv_s0;
    const float wa3 = fmaxf(a3 - nextA, 0.0f) * inv_s0;
    const float wb0 = fmaxf(b0 - b1,    0.0f) * inv_s0;
    const float wb1 = fmaxf(b1 - b2,    0.0f) * inv_s0;
    const float wb2 = fmaxf(b2 - b3,    0.0f) * inv_s0;
    const float wb3 = (sl == 15) ? 0.0f : fmaxf(b3 - b0_next, 0.0f) * inv_s0;

    // ---- store weight tiles (aligned STG.128) ----
    float4* w_out = reinterpret_cast<float4*>(out + N_RAYS * 4);
    w_out[r32 + sl]      = make_float4(wa0, wa1, wa2, wa3);
    w_out[r32 + 16 + sl] = make_float4(wb0, wb1, wb2, wb3);

    // ---- inverse depth partial (fast divides -> MUFU.RCP + FMUL) ----
    float invd = __fdividef(wa0, zA.x) + __fdividef(wa1, zA.y)
               + __fdividef(wa2, zA.z) + __fdividef(wa3, zA.w)
               + __fdividef(wb0, zB.x) + __fdividef(wb1, zB.y)
               + __fdividef(wb2, zB.z) + __fdividef(wb3, zB.w);

    // ---- pixel partials with background folded in ----
    float pr = wa0 * (cA0.x - bg0) + wa1 * (cA0.w - bg0)
             + wa2 * (cA1.z - bg0) + wa3 * (cA2.y - bg0)
             + wb0 * (cB0.x - bg0) + wb1 * (cB0.w - bg0)
             + wb2 * (cB1.z - bg0) + wb3 * (cB2.y - bg0);
    float pg = wa0 * (cA0.y - bg1) + wa1 * (cA1.x - bg1)
             + wa2 * (cA1.w - bg1) + wa3 * (cA2.z - bg1)
             + wb0 * (cB0.y - bg1) + wb1 * (cB1.x - bg1)
             + wb2 * (cB1.w - bg1) + wb3 * (cB2.z - bg1);
    float pb = wa0 * (cA0.z - bg2) + wa1 * (cA1.y - bg2)
             + wa2 * (cA2.x - bg2) + wa3 * (cA2.w - bg2)
             + wb0 * (cB0.z - bg2) + wb1 * (cB1.y - bg2)
             + wb2 * (cB2.x - bg2) + wb3 * (cB2.w - bg2);

    // ---- width-16 butterfly over 4 scalars ----
    #pragma unroll
    for (int off = 8; off > 0; off >>= 1) {
        pr   += __shfl_xor_sync(FULL, pr,   off, 16);
        pg   += __shfl_xor_sync(FULL, pg,   off, 16);
        pb   += __shfl_xor_sync(FULL, pb,   off, 16);
        invd += __shfl_xor_sync(FULL, invd, off, 16);
    }

    if (sl == 0) {
        out[ray * 3 + 0]      = bg0 + pr;
        out[ray * 3 + 1]      = bg1 + pg;
        out[ray * 3 + 2]      = bg2 + pb;
        out[N_RAYS * 3 + ray] = invd;
    }
}

extern "C" void kernel_launch(void* const* d_in, const int* in_sizes, int n_in,
                              void* d_out, int out_size)
{
    const float* sdf   = (const float*)d_in[0];
    const float* color = (const float*)d_in[1];
    const float* z     = (const float*)d_in[2];
    const float* s     = (const float*)d_in[3];
    const float* bg    = (const float*)d_in[4];
    float* out = (float*)d_out;

    const int threads = 256;                 // 8 warps = 16 rays per block
    const int blocks  = N_RAYS / 16;         // 4096
    neus_render_kernel<<<blocks, threads>>>(sdf, color, z, s, bg, out);
}

// round 11
// speedup vs baseline: 1.1566x; 1.0372x over previous
#include <cuda_runtime.h>

// NeuS volume-rendering composite, telescoped:
//   1 - alpha_i = sig_{i+1}/sig_i  =>  trans_i = sig_i / sig_0
//   weight_i = max(sig_i - sig_{i+1}, 0) / sig_0,  weight_0 = weight_{S-1} = 0.
//
// 2 rays per warp (16-lane segments); sub-lane sl owns samples [4sl..4sl+3]
// and [64+4sl..64+4sl+3]. All bulk accesses are aligned float4 with streaming
// (evict-first) cache hints. Background folded into the color sum.
// Persistent grid: exactly 148 SMs x 5 blocks = 740 blocks, grid-stride over
// the 4096 ray tiles -> no partial tail wave (was 5.54 waves at grid=4096).

constexpr int N_RAYS     = 65536;
constexpr int N_SAMPLES  = 128;
constexpr int RAYS_PER_BLOCK = 16;                        // 8 warps x 2 rays
constexpr int N_TILES    = N_RAYS / RAYS_PER_BLOCK;       // 4096
constexpr int PERSISTENT_BLOCKS = 148 * 5;                // 740

__device__ __forceinline__ float fsigmoid(float x) {
    return __fdividef(1.0f, 1.0f + __expf(-x));
}

__device__ __forceinline__ float4 ldcs4(const float4* p) { return __ldcs(p); }

__global__ __launch_bounds__(256, 5)
void neus_render_kernel(const float* __restrict__ sdf,
                        const float* __restrict__ color,
                        const float* __restrict__ z_vals,
                        const float* __restrict__ s_ptr,
                        const float* __restrict__ bg,
                        float* __restrict__ out)
{
    const int lane = threadIdx.x & 31;
    const int sl   = lane & 15;                      // sub-lane in 16-lane segment
    const int warp = threadIdx.x >> 5;
    const int seg  = (warp << 1) + (lane >> 4);      // ray-within-tile (0..15)

    const float s   = __ldg(s_ptr);
    const float bg0 = __ldg(bg + 0);
    const float bg1 = __ldg(bg + 1);
    const float bg2 = __ldg(bg + 2);

    const unsigned FULL = 0xffffffffu;
    const float4* sp = reinterpret_cast<const float4*>(sdf);
    const float4* zp = reinterpret_cast<const float4*>(z_vals);
    const float4* cbase = reinterpret_cast<const float4*>(color);
    float4* w_out = reinterpret_cast<float4*>(out + N_RAYS * 4);

    for (int tile = blockIdx.x; tile < N_TILES; tile += PERSISTENT_BLOCKS) {
        const int ray = tile * RAYS_PER_BLOCK + seg;
        const int r32 = ray * 32;
        const float4* cp = cbase + ray * 96;

        // ---- front-batched loads: 10 aligned LDG.128 per thread ----
        const float4 sdA = ldcs4(sp + r32 + sl);          // samples 4sl..4sl+3
        const float4 sdB = ldcs4(sp + r32 + 16 + sl);     // samples 64+4sl..
        const float4 zA  = ldcs4(zp + r32 + sl);
        const float4 zB  = ldcs4(zp + r32 + 16 + sl);
        const float4 cA0 = ldcs4(cp + sl * 3 + 0);        // r0 g0 b0 r1
        const float4 cA1 = ldcs4(cp + sl * 3 + 1);        // g1 b1 r2 g2
        const float4 cA2 = ldcs4(cp + sl * 3 + 2);        // b2 r3 g3 b3
        const float4 cB0 = ldcs4(cp + 48 + sl * 3 + 0);
        const float4 cB1 = ldcs4(cp + 48 + sl * 3 + 1);
        const float4 cB2 = ldcs4(cp + 48 + sl * 3 + 2);

        // ---- sigmoids ----
        const float a0 = fsigmoid(sdA.x * s), a1 = fsigmoid(sdA.y * s);
        const float a2 = fsigmoid(sdA.z * s), a3 = fsigmoid(sdA.w * s);
        const float b0 = fsigmoid(sdB.x * s), b1 = fsigmoid(sdB.y * s);
        const float b2 = fsigmoid(sdB.z * s), b3 = fsigmoid(sdB.w * s);

        // ---- segment shuffles (width=16) ----
        const float a0_next  = __shfl_down_sync(FULL, a0, 1, 16); // sig(4sl+4)
        const float b0_next  = __shfl_down_sync(FULL, b0, 1, 16); // sig(64+4sl+4)
        const float b0_first = __shfl_sync(FULL, b0, 0, 16);      // sig(sample 64)
        const float sig0     = __shfl_sync(FULL, a0, 0, 16);      // sig(sample 0)
        const float inv_s0   = __fdividef(1.0f, sig0);

        const float nextA = (sl == 15) ? b0_first : a0_next;

        // ---- weights (weight_0 = 0, weight_127 = 0) ----
        const float wa0 = (sl == 0) ? 0.0f : fmaxf(a0 - a1, 0.0f) * inv_s0;
        const float wa1 = fmaxf(a1 - a2,    0.0f) * inv_s0;
        const float wa2 = fmaxf(a2 - a3,    0.0f) * inv_s0;
        const float wa3 = fmaxf(a3 - nextA, 0.0f) * inv_s0;
        const float wb0 = fmaxf(b0 - b1,    0.0f) * inv_s0;
        const float wb1 = fmaxf(b1 - b2,    0.0f) * inv_s0;
        const float wb2 = fmaxf(b2 - b3,    0.0f) * inv_s0;
        const float wb3 = (sl == 15) ? 0.0f : fmaxf(b3 - b0_next, 0.0f) * inv_s0;

        // ---- store weight tiles (streaming STG.128) ----
        __stcs(w_out + r32 + sl,      make_float4(wa0, wa1, wa2, wa3));
        __stcs(w_out + r32 + 16 + sl, make_float4(wb0, wb1, wb2, wb3));

        // ---- inverse depth partial ----
        float invd = __fdividef(wa0, zA.x) + __fdividef(wa1, zA.y)
                   + __fdividef(wa2, zA.z) + __fdividef(wa3, zA.w)
                   + __fdividef(wb0, zB.x) + __fdividef(wb1, zB.y)
                   + __fdividef(wb2, zB.z) + __fdividef(wb3, zB.w);

        // ---- pixel partials with background folded in ----
        float pr = wa0 * (cA0.x - bg0) + wa1 * (cA0.w - bg0)
                 + wa2 * (cA1.z - bg0) + wa3 * (cA2.y - bg0)
                 + wb0 * (cB0.x - bg0) + wb1 * (cB0.w - bg0)
                 + wb2 * (cB1.z - bg0) + wb3 * (cB2.y - bg0);
        float pg = wa0 * (cA0.y - bg1) + wa1 * (cA1.x - bg1)
                 + wa2 * (cA1.w - bg1) + wa3 * (cA2.z - bg1)
                 + wb0 * (cB0.y - bg1) + wb1 * (cB1.x - bg1)
                 + wb2 * (cB1.w - bg1) + wb3 * (cB2.z - bg1);
        float pb = wa0 * (cA0.z - bg2) + wa1 * (cA1.y - bg2)
                 + wa2 * (cA2.x - bg2) + wa3 * (cA2.w - bg2)
                 + wb0 * (cB0.z - bg2) + wb1 * (cB1.y - bg2)
                 + wb2 * (cB2.x - bg2) + wb3 * (cB2.w - bg2);

        // ---- width-16 butterfly over 4 scalars ----
        #pragma unroll
        for (int off = 8; off > 0; off >>= 1) {
            pr   += __shfl_xor_sync(FULL, pr,   off, 16);
            pg   += __shfl_xor_sync(FULL, pg,   off, 16);
            pb   += __shfl_xor_sync(FULL, pb,   off, 16);
            invd += __shfl_xor_sync(FULL, invd, off, 16);
        }

        if (sl == 0) {
            out[ray * 3 + 0]      = bg0 + pr;
            out[ray * 3 + 1]      = bg1 + pg;
            out[ray * 3 + 2]      = bg2 + pb;
            out[N_RAYS * 3 + ray] = invd;
        }
    }
}

extern "C" void kernel_launch(void* const* d_in, const int* in_sizes, int n_in,
                              void* d_out, int out_size)
{
    const float* sdf   = (const float*)d_in[0];
    const float* color = (const float*)d_in[1];
    const float* z     = (const float*)d_in[2];
    const float* s     = (const float*)d_in[3];
    const float* bg    = (const float*)d_in[4];
    float* out = (float*)d_out;

    neus_render_kernel<<<PERSISTENT_BLOCKS, 256>>>(sdf, color, z, s, bg, out);
}